// round 1
// baseline (speedup 1.0000x reference)
#include <cuda_runtime.h>

#define N_ROWS   1000000
#define N_FEAT   100
#define N_BINS   256
#define GRID_B   148
#define ROWS_PER 6784          // 148*6784 >= 1e6 ; every block's row count is a multiple of 32
#define SMEM_BYTES 204800      // 3 warps * 256*32*8  +  1 warp * 256*4*8

// Per-block partial histograms: [block][feature*256 + bin] as float2 (g,h).
// Fully overwritten by every launch -> graph-replay safe, no zeroing needed.
__device__ float2 g_part[GRID_B * N_FEAT * N_BINS];

__global__ __launch_bounds__(128, 1)
void hist_kernel(const int* __restrict__ X,
                 const float* __restrict__ grad,
                 const float* __restrict__ hess)
{
    extern __shared__ unsigned char smem_raw[];

    const int tid  = threadIdx.x;
    const int w    = tid >> 5;
    const int lane = tid & 31;
    const int f    = tid;                 // feature owned by this thread
    const bool act = (f < N_FEAT);

    // Warp-private histogram regions, transposed so bank = f(lane) only:
    // element (f, b) at warpBase + (b*W + lane)*8   (W = lanes used by this warp)
    const int       W      = (w < 3) ? 32 : 4;
    const unsigned  base_w = (w < 3) ? (unsigned)(w * 65536) : 196608u;
    float2* const histT = reinterpret_cast<float2*>(smem_raw + base_w) + lane;

    // ---- zero smem ----
    {
        float4 z = make_float4(0.f, 0.f, 0.f, 0.f);
        float4* s4 = reinterpret_cast<float4*>(smem_raw);
        for (int i = tid; i < SMEM_BYTES / 16; i += 128) s4[i] = z;
    }
    __syncthreads();

    const int rowStart = blockIdx.x * ROWS_PER;
    const int rowEnd   = min(rowStart + ROWS_PER, N_ROWS);
    const int nsc      = (rowEnd - rowStart) >> 5;   // whole 32-row superchunks (always exact)

    const int* xcol = X + rowStart * N_FEAT + f;

    // ---- load one 32-row superchunk of bins (+ per-lane g/h for shfl broadcast) ----
    auto loadSC = [&](int s, int (&bins)[32], float& gp, float& hp) {
        const int* p = xcol + s * (32 * N_FEAT);
#pragma unroll
        for (int k = 0; k < 32; ++k)
            bins[k] = act ? __ldg(p + k * N_FEAT) : 0;
        const int r = rowStart + s * 32 + lane;
        gp = __ldg(grad + r);
        hp = __ldg(hess + r);
    };

    // ---- process one superchunk: chunks of 4 rows, duplicate-merged, batched RMW ----
    auto processSC = [&](const int (&bins)[32], float gp, float hp) {
#pragma unroll
        for (int c = 0; c < 8; ++c) {
            const int k = 4 * c;
            int b0 = bins[k], b1 = bins[k + 1], b2 = bins[k + 2], b3 = bins[k + 3];
            float g0 = __shfl_sync(0xffffffffu, gp, k);
            float h0 = __shfl_sync(0xffffffffu, hp, k);
            float g1 = __shfl_sync(0xffffffffu, gp, k + 1);
            float h1 = __shfl_sync(0xffffffffu, hp, k + 1);
            float g2 = __shfl_sync(0xffffffffu, gp, k + 2);
            float h2 = __shfl_sync(0xffffffffu, hp, k + 2);
            float g3 = __shfl_sync(0xffffffffu, gp, k + 3);
            float h3 = __shfl_sync(0xffffffffu, hp, k + 3);

            // Duplicate-bin merge (parallel form on original values).
            const bool p01 = (b0 == b1), p02 = (b0 == b2), p03 = (b0 == b3);
            const bool p12 = (b1 == b2), p13 = (b1 == b3), p23 = (b2 == b3);

            float G0 = g0, H0 = h0, G1 = g1, H1 = h1, G2 = g2, H2 = h2, G3 = g3, H3 = h3;
            if (p01) { G1 += g0; H1 += h0; }
            if (p02) { G2 += g0; H2 += h0; }
            if (p12) { G2 += g1; H2 += h1; }
            if (p03) { G3 += g0; H3 += h0; }
            if (p13) { G3 += g1; H3 += h1; }
            if (p23) { G3 += g2; H3 += h2; }
            if (p01 | p02 | p03) { G0 = 0.f; H0 = 0.f; }
            if (p12 | p13)       { G1 = 0.f; H1 = 0.f; }
            if (p23)             { G2 = 0.f; H2 = 0.f; }

            if (act) {
                // Batched RMW; warp-order smem execution keeps aliased stores correct.
                float2 v0 = histT[b0 * W];
                float2 v1 = histT[b1 * W];
                float2 v2 = histT[b2 * W];
                float2 v3 = histT[b3 * W];
                v0.x += G0; v0.y += H0;
                v1.x += G1; v1.y += H1;
                v2.x += G2; v2.y += H2;
                v3.x += G3; v3.y += H3;
                histT[b0 * W] = v0;
                histT[b1 * W] = v1;
                histT[b2 * W] = v2;
                histT[b3 * W] = v3;
            }
        }
    };

    // ---- double-buffered main loop (nsc is even: 212 or 86) ----
    int binsA[32], binsB[32];
    float gA, hA, gB, hB;
    loadSC(0, binsA, gA, hA);
    for (int s = 0; s < nsc; s += 2) {
        if (s + 1 < nsc) loadSC(s + 1, binsB, gB, hB);
        processSC(binsA, gA, hA);
        if (s + 1 >= nsc) break;
        if (s + 2 < nsc) loadSC(s + 2, binsA, gA, hA);
        processSC(binsB, gB, hB);
    }

    __syncthreads();

    // ---- dump private histogram -> global partial (bank-conflict-free reads) ----
    if (act) {
        float2* myPart = g_part + blockIdx.x * (N_FEAT * N_BINS) + f * N_BINS;
#pragma unroll 4
        for (int b = 0; b < N_BINS; ++b)
            myPart[b] = histT[b * W];
    }
}

// One block per feature: reduce 148 partials, inclusive scan over 256 bins,
// write Gl at [f*256+b], Hl at [25600 + f*256+b].
__global__ __launch_bounds__(256)
void reduce_scan_kernel(float* __restrict__ out)
{
    const int f   = blockIdx.x;
    const int tid = threadIdx.x;

    const float2* p = g_part + f * N_BINS + tid;
    float2 a0 = make_float2(0.f, 0.f), a1 = a0, a2 = a0, a3 = a0;
#pragma unroll 4
    for (int blk = 0; blk < GRID_B; blk += 4) {     // 148 = 4*37
        float2 v0 = p[(blk + 0) * (N_FEAT * N_BINS)];
        float2 v1 = p[(blk + 1) * (N_FEAT * N_BINS)];
        float2 v2 = p[(blk + 2) * (N_FEAT * N_BINS)];
        float2 v3 = p[(blk + 3) * (N_FEAT * N_BINS)];
        a0.x += v0.x; a0.y += v0.y;
        a1.x += v1.x; a1.y += v1.y;
        a2.x += v2.x; a2.y += v2.y;
        a3.x += v3.x; a3.y += v3.y;
    }
    float2 acc;
    acc.x = (a0.x + a1.x) + (a2.x + a3.x);
    acc.y = (a0.y + a1.y) + (a2.y + a3.y);

    __shared__ float2 buf[N_BINS];
    buf[tid] = acc;
    __syncthreads();
#pragma unroll
    for (int off = 1; off < N_BINS; off <<= 1) {
        float2 t = make_float2(0.f, 0.f);
        const bool pred = (tid >= off);
        if (pred) t = buf[tid - off];
        __syncthreads();
        if (pred) { buf[tid].x += t.x; buf[tid].y += t.y; }
        __syncthreads();
    }
    float2 r = buf[tid];
    out[f * N_BINS + tid]                     = r.x;   // Gl
    out[N_FEAT * N_BINS + f * N_BINS + tid]   = r.y;   // Hl
}

extern "C" void kernel_launch(void* const* d_in, const int* in_sizes, int n_in,
                              void* d_out, int out_size)
{
    const int*   X = (const int*)d_in[0];
    const float* g = (const float*)d_in[1];
    const float* h = (const float*)d_in[2];
    float* out = (float*)d_out;

    // Attribute persists from the first (non-captured) call; ignore errors during capture.
    (void)cudaFuncSetAttribute(hist_kernel,
                               cudaFuncAttributeMaxDynamicSharedMemorySize, SMEM_BYTES);

    hist_kernel<<<GRID_B, 128, SMEM_BYTES>>>(X, g, h);
    reduce_scan_kernel<<<N_FEAT, 256>>>(out);
}

// round 3
// speedup vs baseline: 1.0972x; 1.0972x over previous
#include <cuda_runtime.h>

#define N_ROWS   1000000
#define N_FEAT   100
#define N_BINS   256
#define GRID_B   148
#define ROWS_PER 6784            // 147*6784 + 2752 = 1e6; every block's count is a multiple of 32
#define SMEM_BYTES 204800        // 2 halves * (3 warps*256*32*4 + 1 warp*256*4*4)
#define HALF_BYTES 102400

// Per-block partial histograms, scalar floats: [block][half][feature][bin].
// half 0 = gradient, half 1 = hessian. Fully overwritten every launch.
__device__ float  g_part[GRID_B * 2 * N_FEAT * N_BINS];
// Stage-1 reduced partials: [feature][quarter][bin] as float2 (g,h).
__device__ float2 g_red[N_FEAT * 4 * N_BINS];

__global__ __launch_bounds__(256, 1)
void hist_kernel(const int* __restrict__ X,
                 const float* __restrict__ grad,
                 const float* __restrict__ hess)
{
    extern __shared__ unsigned char smem_raw[];

    const int tid  = threadIdx.x;
    const int w    = tid >> 5;
    const int lane = tid & 31;
    const int half = w >> 2;             // 0: gradient, 1: hessian
    const int w3   = w & 3;              // warp index within half
    const int f    = tid & 127;          // feature owned by this thread
    const bool act = (f < N_FEAT);
    const float* __restrict__ val = half ? hess : grad;

    // Transposed warp-private region: element (lane, b) at base + (b<<sh) + lane*4.
    // Full warps (w3<3): W=32 -> bank = lane (conflict-free).
    // Tail warp (w3==3): W=4, only 4 active lanes -> conflict-free among them.
    const int      sh   = (w3 < 3) ? 7 : 4;                       // b*W*4 = b<<sh
    const unsigned base = half * HALF_BYTES +
                          ((w3 < 3) ? (unsigned)(w3 * 32768) : 98304u);
    unsigned char* const histBase = smem_raw + base + lane * 4;

    // ---- zero smem ----
    {
        float4 z = make_float4(0.f, 0.f, 0.f, 0.f);
        float4* s4 = reinterpret_cast<float4*>(smem_raw);
        for (int i = tid; i < SMEM_BYTES / 16; i += 256) s4[i] = z;
    }
    __syncthreads();

    const int rowStart = blockIdx.x * ROWS_PER;
    const int rowEnd   = min(rowStart + ROWS_PER, N_ROWS);
    const int nsc      = (rowEnd - rowStart) >> 5;   // exact (212 or 86)

    const int* xcol = X + rowStart * N_FEAT + f;

    // ---- load one 32-row superchunk: bins + broadcast g/h values (LDG.128) ----
    auto loadSC = [&](int s, int (&bins)[32], float4 (&gv)[8]) {
        const int* p = xcol + s * (32 * N_FEAT);
#pragma unroll
        for (int k = 0; k < 32; ++k)
            bins[k] = act ? __ldg(p + k * N_FEAT) : 0;
        const float4* vp = reinterpret_cast<const float4*>(val + rowStart + s * 32);
#pragma unroll
        for (int c = 0; c < 8; ++c)
            gv[c] = __ldg(vp + c);       // same address warp-wide -> broadcast
    };

    // ---- process one superchunk: 4-row chunks, duplicate-merged, batched RMW ----
    auto processSC = [&](const int (&bins)[32], const float4 (&gv)[8]) {
#pragma unroll
        for (int c = 0; c < 8; ++c) {
            const int k = 4 * c;
            const int b0 = bins[k], b1 = bins[k + 1], b2 = bins[k + 2], b3 = bins[k + 3];
            const float g0 = gv[c].x, g1 = gv[c].y, g2 = gv[c].z, g3 = gv[c].w;

            const bool p01 = (b0 == b1), p02 = (b0 == b2), p03 = (b0 == b3);
            const bool p12 = (b1 == b2), p13 = (b1 == b3), p23 = (b2 == b3);

            float G0 = g0, G1 = g1, G2 = g2, G3 = g3;
            if (p01) G1 += g0;
            if (p02) G2 += g0;
            if (p12) G2 += g1;
            if (p03) G3 += g0;
            if (p13) G3 += g1;
            if (p23) G3 += g2;
            if (p01 | p02 | p03) G0 = 0.f;
            if (p12 | p13)       G1 = 0.f;
            if (p23)             G2 = 0.f;

            if (act) {
                float* a0 = reinterpret_cast<float*>(histBase + ((unsigned)b0 << sh));
                float* a1 = reinterpret_cast<float*>(histBase + ((unsigned)b1 << sh));
                float* a2 = reinterpret_cast<float*>(histBase + ((unsigned)b2 << sh));
                float* a3 = reinterpret_cast<float*>(histBase + ((unsigned)b3 << sh));
                float v0 = *a0, v1 = *a1, v2 = *a2, v3 = *a3;
                v0 += G0; v1 += G1; v2 += G2; v3 += G3;
                *a0 = v0; *a1 = v1; *a2 = v2; *a3 = v3;   // in-order: last alias wins
            }
        }
    };

    // ---- double-buffered main loop (nsc is even) ----
    int   binsA[32], binsB[32];
    float4 gvA[8], gvB[8];
    loadSC(0, binsA, gvA);
    for (int s = 0; s < nsc; s += 2) {
        loadSC(s + 1, binsB, gvB);
        processSC(binsA, gvA);
        if (s + 2 < nsc) loadSC(s + 2, binsA, gvA);
        processSC(binsB, gvB);
    }

    __syncthreads();

    // ---- dump private histogram -> global partials (vectorized STG.128) ----
    if (act) {
        float4* myPart = reinterpret_cast<float4*>(
            g_part + ((blockIdx.x * 2 + half) * N_FEAT + f) * N_BINS);
#pragma unroll 4
        for (int b = 0; b < N_BINS; b += 4) {
            float4 v;
            v.x = *reinterpret_cast<float*>(histBase + ((unsigned)(b + 0) << sh));
            v.y = *reinterpret_cast<float*>(histBase + ((unsigned)(b + 1) << sh));
            v.z = *reinterpret_cast<float*>(histBase + ((unsigned)(b + 2) << sh));
            v.w = *reinterpret_cast<float*>(histBase + ((unsigned)(b + 3) << sh));
            myPart[b >> 2] = v;
        }
    }
}

// Stage 1: 400 blocks, block (f, q) reduces 37 of the 148 partials.
__global__ __launch_bounds__(256)
void reduce1_kernel()
{
    const int f   = blockIdx.x >> 2;
    const int q   = blockIdx.x & 3;
    const int tid = threadIdx.x;

    float gs = 0.f, hs = 0.f;
    const int blk0 = q * 37;
#pragma unroll 4
    for (int i = 0; i < 37; ++i) {
        const int blk = blk0 + i;
        gs += g_part[((blk * 2 + 0) * N_FEAT + f) * N_BINS + tid];
        hs += g_part[((blk * 2 + 1) * N_FEAT + f) * N_BINS + tid];
    }
    g_red[(f * 4 + q) * N_BINS + tid] = make_float2(gs, hs);
}

// Stage 2: 100 blocks, reduce 4 quarters + inclusive scan over 256 bins.
__global__ __launch_bounds__(256)
void reduce2_kernel(float* __restrict__ out)
{
    const int f   = blockIdx.x;
    const int tid = threadIdx.x;

    float2 acc = make_float2(0.f, 0.f);
#pragma unroll
    for (int q = 0; q < 4; ++q) {
        float2 v = g_red[(f * 4 + q) * N_BINS + tid];
        acc.x += v.x; acc.y += v.y;
    }

    __shared__ float2 buf[N_BINS];
    buf[tid] = acc;
    __syncthreads();
#pragma unroll
    for (int off = 1; off < N_BINS; off <<= 1) {
        float2 t = make_float2(0.f, 0.f);
        const bool pred = (tid >= off);
        if (pred) t = buf[tid - off];
        __syncthreads();
        if (pred) { buf[tid].x += t.x; buf[tid].y += t.y; }
        __syncthreads();
    }
    float2 r = buf[tid];
    out[f * N_BINS + tid]                   = r.x;   // Gl
    out[N_FEAT * N_BINS + f * N_BINS + tid] = r.y;   // Hl
}

extern "C" void kernel_launch(void* const* d_in, const int* in_sizes, int n_in,
                              void* d_out, int out_size)
{
    const int*   X = (const int*)d_in[0];
    const float* g = (const float*)d_in[1];
    const float* h = (const float*)d_in[2];
    float* out = (float*)d_out;

    (void)cudaFuncSetAttribute(hist_kernel,
                               cudaFuncAttributeMaxDynamicSharedMemorySize, SMEM_BYTES);

    hist_kernel<<<GRID_B, 256, SMEM_BYTES>>>(X, g, h);
    reduce1_kernel<<<N_FEAT * 4, 256>>>();
    reduce2_kernel<<<N_FEAT, 256>>>(out);
}